// round 5
// baseline (speedup 1.0000x reference)
#include <cuda_runtime.h>

#define NN 50000
#define NE 1250000
#define DIM 64
#define EPS_C 1e-7f
#define SCAN_T 1024
#define CHUNK ((NN + SCAN_T - 1) / SCAN_T)   // 49

// Counting-sort scratch (static device memory; no allocation)
__device__ int g_cnt[NN];
__device__ int g_start[NN + 1];
__device__ int g_cur[NN];
__device__ unsigned int g_edges[NE];

// ---------------------------------------------------------------------------
// Pass 0: zero the histogram counters
// ---------------------------------------------------------------------------
__global__ void __launch_bounds__(256) zero_cnt_kernel() {
    int i = blockIdx.x * blockDim.x + threadIdx.x;
    if (i < NN) g_cnt[i] = 0;
}

// ---------------------------------------------------------------------------
// Pass 1: degree histogram
// ---------------------------------------------------------------------------
__global__ void __launch_bounds__(256) hist_kernel(const int* __restrict__ dst, int E) {
    int e = blockIdx.x * blockDim.x + threadIdx.x;
    if (e < E) atomicAdd(&g_cnt[dst[e]], 1);
}

// ---------------------------------------------------------------------------
// Pass 2: single-block exclusive scan over 50K counters -> g_start / g_cur
// ---------------------------------------------------------------------------
__global__ void __launch_bounds__(SCAN_T) scan_kernel(int N, int E) {
    __shared__ int s[SCAN_T];
    int t = threadIdx.x;
    int base = t * CHUNK;
    int mysum = 0;
    #pragma unroll 1
    for (int i = 0; i < CHUNK; i++) {
        int idx = base + i;
        if (idx < N) mysum += g_cnt[idx];
    }
    s[t] = mysum;
    __syncthreads();
    // Hillis-Steele inclusive scan
    for (int off = 1; off < SCAN_T; off <<= 1) {
        int v = (t >= off) ? s[t - off] : 0;
        __syncthreads();
        s[t] += v;
        __syncthreads();
    }
    int run = s[t] - mysum;   // exclusive base for this thread's chunk
    #pragma unroll 1
    for (int i = 0; i < CHUNK; i++) {
        int idx = base + i;
        if (idx < N) {
            g_start[idx] = run;
            g_cur[idx]   = run;
            run += g_cnt[idx];
        }
    }
    if (t == SCAN_T - 1) g_start[N] = E;
}

// ---------------------------------------------------------------------------
// Pass 3: scatter packed edges into dst-sorted order
//   packed = src (16b) | ef0 (3b @16) | ef1 (2b @19)
// ---------------------------------------------------------------------------
__global__ void __launch_bounds__(256)
scatter_kernel(const int* __restrict__ src,
               const int* __restrict__ dst,
               const int* __restrict__ ef0,
               const int* __restrict__ ef1, int E) {
    int e = blockIdx.x * blockDim.x + threadIdx.x;
    if (e < E) {
        int pos = atomicAdd(&g_cur[dst[e]], 1);
        g_edges[pos] = (unsigned)src[e] | ((unsigned)ef0[e] << 16)
                                        | ((unsigned)ef1[e] << 19);
    }
}

// ---------------------------------------------------------------------------
// Pass 4: fused per-node aggregation + MessageNorm + residual + GEMM.
// One warp per node; lane owns dims {2*lane, 2*lane+1}.
// Softmax needs no max-shift: m <= ~12 so exp is fp32-safe, result identical.
// ---------------------------------------------------------------------------
__global__ void __launch_bounds__(256)
main_kernel(const float* __restrict__ nf,
            const float* __restrict__ emb0,
            const float* __restrict__ emb1,
            const float* __restrict__ W,
            const float* __restrict__ b,
            const float* __restrict__ beta,
            const float* __restrict__ scale,
            float* __restrict__ out, int N) {
    __shared__ float  sW[DIM * DIM];   // 16 KB
    __shared__ float  sb[DIM];
    __shared__ float2 se0[8 * 32];
    __shared__ float2 se1[4 * 32];
    int tid = threadIdx.x;
    for (int i = tid; i < DIM * DIM; i += 256) sW[i] = W[i];
    if (tid < DIM)     sb[tid]  = b[tid];
    if (tid < 8 * 32)  se0[tid] = reinterpret_cast<const float2*>(emb0)[tid];
    if (tid < 4 * 32)  se1[tid] = reinterpret_cast<const float2*>(emb1)[tid];
    __syncthreads();

    const int lane = tid & 31;
    const int node = blockIdx.x * 8 + (tid >> 5);
    if (node >= N) return;

    const float  B   = beta[0];
    const float2* nf2 = reinterpret_cast<const float2*>(nf);

    const int s0 = g_start[node];
    const int s1 = g_start[node + 1];

    float aE0 = 0.f, aE1 = 0.f, aM0 = 0.f, aM1 = 0.f;

    for (int base = s0; base < s1; base += 32) {
        int nrem = min(32, s1 - base);
        unsigned pk = (lane < nrem) ? g_edges[base + lane] : 0u;
        #pragma unroll 4
        for (int j = 0; j < nrem; j++) {
            unsigned p = __shfl_sync(0xFFFFFFFFu, pk, j);
            int sidx = p & 0xFFFF;
            int f0   = (p >> 16) & 7;
            int f1   = (p >> 19) & 3;
            float2 x  = nf2[sidx * 32 + lane];
            float2 e0 = se0[f0 * 32 + lane];
            float2 e1 = se1[f1 * 32 + lane];
            float m0 = fmaxf(x.x + e0.x + e1.x, 0.f) + EPS_C;
            float m1 = fmaxf(x.y + e0.y + e1.y, 0.f) + EPS_C;
            float ex0 = __expf(m0 * B);
            float ex1 = __expf(m1 * B);
            aE0 += ex0; aM0 += m0 * ex0;
            aE1 += ex1; aM1 += m1 * ex1;
        }
    }

    float msg0 = (aE0 > 0.f) ? aM0 / aE0 : 0.f;
    float msg1 = (aE1 > 0.f) ? aM1 / aE1 : 0.f;

    float2 x = nf2[node * 32 + lane];
    float smsg = msg0 * msg0 + msg1 * msg1;
    float snf  = x.x * x.x + x.y * x.y;
    #pragma unroll
    for (int o = 16; o; o >>= 1) {
        smsg += __shfl_xor_sync(0xFFFFFFFFu, smsg, o);
        snf  += __shfl_xor_sync(0xFFFFFFFFu, snf,  o);
    }
    float coef = sqrtf(snf) * scale[0] / fmaxf(sqrtf(smsg), 1e-12f);
    float f0v = x.x + msg0 * coef;
    float f1v = x.y + msg1 * coef;

    float acc0 = sb[lane * 2];
    float acc1 = sb[lane * 2 + 1];
    #pragma unroll
    for (int k = 0; k < 32; k++) {
        float g0 = __shfl_sync(0xFFFFFFFFu, f0v, k);   // feats[2k]
        float g1 = __shfl_sync(0xFFFFFFFFu, f1v, k);   // feats[2k+1]
        float2 w0 = reinterpret_cast<const float2*>(sW)[(2 * k)     * 32 + lane];
        float2 w1 = reinterpret_cast<const float2*>(sW)[(2 * k + 1) * 32 + lane];
        acc0 += g0 * w0.x + g1 * w1.x;
        acc1 += g0 * w0.y + g1 * w1.y;
    }
    reinterpret_cast<float2*>(out)[node * 32 + lane] = make_float2(acc0, acc1);
}

// ---------------------------------------------------------------------------
extern "C" void kernel_launch(void* const* d_in, const int* in_sizes, int n_in,
                              void* d_out, int out_size) {
    const float* nf    = (const float*)d_in[0];
    const float* emb0  = (const float*)d_in[1];
    const float* emb1  = (const float*)d_in[2];
    const float* W     = (const float*)d_in[3];
    const float* b     = (const float*)d_in[4];
    const float* beta  = (const float*)d_in[5];
    const float* scale = (const float*)d_in[6];
    const int*   src   = (const int*)d_in[7];
    const int*   dst   = (const int*)d_in[8];
    const int*   ef0   = (const int*)d_in[9];
    const int*   ef1   = (const int*)d_in[10];

    const int E = in_sizes[7];
    const int N = in_sizes[0] / DIM;

    zero_cnt_kernel<<<(NN + 255) / 256, 256>>>();
    hist_kernel<<<(E + 255) / 256, 256>>>(dst, E);
    scan_kernel<<<1, SCAN_T>>>(N, E);
    scatter_kernel<<<(E + 255) / 256, 256>>>(src, dst, ef0, ef1, E);
    main_kernel<<<(N + 7) / 8, 256>>>(nf, emb0, emb1, W, b, beta, scale,
                                      (float*)d_out, N);
}